// round 1
// baseline (speedup 1.0000x reference)
#include <cuda_runtime.h>
#include <cuda_bf16.h>

#define NUM_CLASSES 5
#define NBLK 1024
#define NTHR 256

// Per-block partials, class-major for coalesced finalize reads.
// Fully rewritten by every main-kernel launch -> graph-replay safe, no init needed.
__device__ float g_psum[NUM_CLASSES * NBLK];
__device__ float g_pcnt[NUM_CLASSES * NBLK];

__global__ __launch_bounds__(NTHR) void mfe_main_kernel(
    const float4* __restrict__ in4,   // inputs viewed as float4 (5 float4 per 4 rows)
    const int4*   __restrict__ tg4,   // targets viewed as int4 (4 rows per load)
    int ngroups)                      // number of 4-row groups
{
    float lsum[NUM_CLASSES];
    float lcnt[NUM_CLASSES];
#pragma unroll
    for (int c = 0; c < NUM_CLASSES; c++) { lsum[c] = 0.f; lcnt[c] = 0.f; }

    const int stride = NBLK * NTHR;
    for (int g = blockIdx.x * NTHR + threadIdx.x; g < ngroups; g += stride) {
        // 4 rows x 5 floats = 5 aligned float4 loads
        const float4 v0 = in4[5 * g + 0];
        const float4 v1 = in4[5 * g + 1];
        const float4 v2 = in4[5 * g + 2];
        const float4 v3 = in4[5 * g + 3];
        const float4 v4 = in4[5 * g + 4];
        const int4  tt4 = tg4[g];

        float x[20];
        x[0]=v0.x; x[1]=v0.y; x[2]=v0.z; x[3]=v0.w;
        x[4]=v1.x; x[5]=v1.y; x[6]=v1.z; x[7]=v1.w;
        x[8]=v2.x; x[9]=v2.y; x[10]=v2.z; x[11]=v2.w;
        x[12]=v3.x; x[13]=v3.y; x[14]=v3.z; x[15]=v3.w;
        x[16]=v4.x; x[17]=v4.y; x[18]=v4.z; x[19]=v4.w;

        int tgt[4];
        tgt[0] = tt4.x; tgt[1] = tt4.y; tgt[2] = tt4.z; tgt[3] = tt4.w;

#pragma unroll
        for (int r = 0; r < 4; r++) {
            const float a0 = x[5 * r + 0];
            const float a1 = x[5 * r + 1];
            const float a2 = x[5 * r + 2];
            const float a3 = x[5 * r + 3];
            const float a4 = x[5 * r + 4];
            const float m  = fmaxf(fmaxf(fmaxf(a0, a1), fmaxf(a2, a3)), a4);
            const float s  = __expf(a0 - m) + __expf(a1 - m) + __expf(a2 - m)
                           + __expf(a3 - m) + __expf(a4 - m);
            const int   t  = tgt[r];
            // select x[t] without dynamic indexing (avoid local-mem spill)
            float xt = a0;
            xt = (t == 1) ? a1 : xt;
            xt = (t == 2) ? a2 : xt;
            xt = (t == 3) ? a3 : xt;
            xt = (t == 4) ? a4 : xt;
            const float loss = __logf(s) + m - xt;
#pragma unroll
            for (int c = 0; c < NUM_CLASSES; c++) {
                const bool hit = (t == c);
                lsum[c] += hit ? loss : 0.f;
                lcnt[c] += hit ? 1.f  : 0.f;
            }
        }
    }

    // warp shuffle reduce (10 values)
#pragma unroll
    for (int o = 16; o > 0; o >>= 1) {
#pragma unroll
        for (int c = 0; c < NUM_CLASSES; c++) {
            lsum[c] += __shfl_down_sync(0xFFFFFFFFu, lsum[c], o);
            lcnt[c] += __shfl_down_sync(0xFFFFFFFFu, lcnt[c], o);
        }
    }

    __shared__ float ssum[NTHR / 32][NUM_CLASSES];
    __shared__ float scnt[NTHR / 32][NUM_CLASSES];
    const int wid = threadIdx.x >> 5;
    const int lid = threadIdx.x & 31;
    if (lid == 0) {
#pragma unroll
        for (int c = 0; c < NUM_CLASSES; c++) { ssum[wid][c] = lsum[c]; scnt[wid][c] = lcnt[c]; }
    }
    __syncthreads();
    if (threadIdx.x == 0) {
#pragma unroll
        for (int c = 0; c < NUM_CLASSES; c++) {
            float s = 0.f, n = 0.f;
#pragma unroll
            for (int w = 0; w < NTHR / 32; w++) { s += ssum[w][c]; n += scnt[w][c]; }
            g_psum[c * NBLK + blockIdx.x] = s;
            g_pcnt[c * NBLK + blockIdx.x] = n;
        }
    }
}

__global__ __launch_bounds__(NTHR) void mfe_final_kernel(
    float* __restrict__ out,
    const float* __restrict__ inputs,  // for remainder rows (unused when rows%4==0)
    const int*   __restrict__ targets,
    int rem_start, int nrows)
{
    __shared__ float red[NTHR];
    __shared__ float cls_sum[NUM_CLASSES];
    __shared__ float cls_cnt[NUM_CLASSES];

    for (int c = 0; c < NUM_CLASSES; c++) {
        float s = 0.f, n = 0.f;
        for (int i = threadIdx.x; i < NBLK; i += NTHR) {
            s += g_psum[c * NBLK + i];
            n += g_pcnt[c * NBLK + i];
        }
        red[threadIdx.x] = s;
        __syncthreads();
        for (int o = NTHR / 2; o > 0; o >>= 1) {
            if (threadIdx.x < o) red[threadIdx.x] += red[threadIdx.x + o];
            __syncthreads();
        }
        if (threadIdx.x == 0) cls_sum[c] = red[0];
        __syncthreads();
        red[threadIdx.x] = n;
        __syncthreads();
        for (int o = NTHR / 2; o > 0; o >>= 1) {
            if (threadIdx.x < o) red[threadIdx.x] += red[threadIdx.x + o];
            __syncthreads();
        }
        if (threadIdx.x == 0) cls_cnt[c] = red[0];
        __syncthreads();
    }

    if (threadIdx.x == 0) {
        // remainder rows not covered by 4-row groups (dead code when nrows%4==0)
        for (int r = rem_start; r < nrows; r++) {
            float a[NUM_CLASSES];
            float m = -1e30f;
            for (int c = 0; c < NUM_CLASSES; c++) {
                a[c] = inputs[r * NUM_CLASSES + c];
                m = fmaxf(m, a[c]);
            }
            float s = 0.f;
            for (int c = 0; c < NUM_CLASSES; c++) s += __expf(a[c] - m);
            const int t = targets[r];
            const float loss = __logf(s) + m - a[t];
            cls_sum[t] += loss;
            cls_cnt[t] += 1.f;
        }
        float total = 0.f;
        for (int c = 0; c < NUM_CLASSES; c++) {
            const float n = cls_cnt[c];
            total += (n > 0.f) ? (cls_sum[c] / n) : 0.f;
        }
        out[0] = total;
    }
}

extern "C" void kernel_launch(void* const* d_in, const int* in_sizes, int n_in,
                              void* d_out, int out_size)
{
    const float* inputs  = (const float*)d_in[0];
    const int*   targets = (const int*)d_in[1];
    float*       out     = (float*)d_out;

    const int nrows   = in_sizes[0] / NUM_CLASSES;
    const int ngroups = nrows / 4;              // 4 rows per thread-iteration
    const int rem     = ngroups * 4;            // first remainder row

    mfe_main_kernel<<<NBLK, NTHR>>>(
        (const float4*)inputs, (const int4*)targets, ngroups);
    mfe_final_kernel<<<1, NTHR>>>(out, inputs, targets, rem, nrows);
}

// round 2
// speedup vs baseline: 1.3735x; 1.3735x over previous
#include <cuda_runtime.h>
#include <cuda_bf16.h>

#define NUM_CLASSES 5
#define NBLK 1024
#define NTHR 256

// Per-block partials, class-major: g_psum[c*NBLK + b].
// Fully rewritten by every main-kernel launch -> graph-replay safe, no init needed.
__device__ float g_psum[NUM_CLASSES * NBLK];
__device__ float g_pcnt[NUM_CLASSES * NBLK];

__global__ __launch_bounds__(NTHR) void mfe_main_kernel(
    const float4* __restrict__ in4,   // inputs viewed as float4 (5 float4 per 4 rows)
    const int4*   __restrict__ tg4,   // targets viewed as int4 (4 rows per load)
    int ngroups)                      // number of 4-row groups
{
    float lsum[NUM_CLASSES];
    float lcnt[NUM_CLASSES];
#pragma unroll
    for (int c = 0; c < NUM_CLASSES; c++) { lsum[c] = 0.f; lcnt[c] = 0.f; }

    const int stride = NBLK * NTHR;
    for (int g = blockIdx.x * NTHR + threadIdx.x; g < ngroups; g += stride) {
        // 4 rows x 5 floats = 5 aligned float4 loads
        const float4 v0 = in4[5 * g + 0];
        const float4 v1 = in4[5 * g + 1];
        const float4 v2 = in4[5 * g + 2];
        const float4 v3 = in4[5 * g + 3];
        const float4 v4 = in4[5 * g + 4];
        const int4  tt4 = tg4[g];

        float x[20];
        x[0]=v0.x; x[1]=v0.y; x[2]=v0.z; x[3]=v0.w;
        x[4]=v1.x; x[5]=v1.y; x[6]=v1.z; x[7]=v1.w;
        x[8]=v2.x; x[9]=v2.y; x[10]=v2.z; x[11]=v2.w;
        x[12]=v3.x; x[13]=v3.y; x[14]=v3.z; x[15]=v3.w;
        x[16]=v4.x; x[17]=v4.y; x[18]=v4.z; x[19]=v4.w;

        int tgt[4];
        tgt[0] = tt4.x; tgt[1] = tt4.y; tgt[2] = tt4.z; tgt[3] = tt4.w;

#pragma unroll
        for (int r = 0; r < 4; r++) {
            const float a0 = x[5 * r + 0];
            const float a1 = x[5 * r + 1];
            const float a2 = x[5 * r + 2];
            const float a3 = x[5 * r + 3];
            const float a4 = x[5 * r + 4];
            const float m  = fmaxf(fmaxf(fmaxf(a0, a1), fmaxf(a2, a3)), a4);
            const float s  = __expf(a0 - m) + __expf(a1 - m) + __expf(a2 - m)
                           + __expf(a3 - m) + __expf(a4 - m);
            const int   t  = tgt[r];
            // select x[t] without dynamic indexing (avoid local-mem spill)
            float xt = a0;
            xt = (t == 1) ? a1 : xt;
            xt = (t == 2) ? a2 : xt;
            xt = (t == 3) ? a3 : xt;
            xt = (t == 4) ? a4 : xt;
            const float loss = __logf(s) + m - xt;
#pragma unroll
            for (int c = 0; c < NUM_CLASSES; c++) {
                const bool hit = (t == c);
                lsum[c] += hit ? loss : 0.f;
                lcnt[c] += hit ? 1.f  : 0.f;
            }
        }
    }

    // warp shuffle reduce (10 values)
#pragma unroll
    for (int o = 16; o > 0; o >>= 1) {
#pragma unroll
        for (int c = 0; c < NUM_CLASSES; c++) {
            lsum[c] += __shfl_down_sync(0xFFFFFFFFu, lsum[c], o);
            lcnt[c] += __shfl_down_sync(0xFFFFFFFFu, lcnt[c], o);
        }
    }

    __shared__ float ssum[NTHR / 32][NUM_CLASSES];
    __shared__ float scnt[NTHR / 32][NUM_CLASSES];
    const int wid = threadIdx.x >> 5;
    const int lid = threadIdx.x & 31;
    if (lid == 0) {
#pragma unroll
        for (int c = 0; c < NUM_CLASSES; c++) { ssum[wid][c] = lsum[c]; scnt[wid][c] = lcnt[c]; }
    }
    __syncthreads();
    if (threadIdx.x == 0) {
#pragma unroll
        for (int c = 0; c < NUM_CLASSES; c++) {
            float s = 0.f, n = 0.f;
#pragma unroll
            for (int w = 0; w < NTHR / 32; w++) { s += ssum[w][c]; n += scnt[w][c]; }
            g_psum[c * NBLK + blockIdx.x] = s;
            g_pcnt[c * NBLK + blockIdx.x] = n;
        }
    }
}

// Finalize: one block, 256 threads. NBLK=1024 floats per class = 256 float4
// per class, so the float4 at flat index 256*c + t holds 4 class-c partials.
// Each thread issues all 10 independent float4 loads up front (MLP=10, one
// DRAM wave) instead of 40 serialized strided waves.
__global__ __launch_bounds__(NTHR) void mfe_final_kernel(
    float* __restrict__ out,
    const float* __restrict__ inputs,  // for remainder rows (unused when rows%4==0)
    const int*   __restrict__ targets,
    int rem_start, int nrows)
{
    const int tid = threadIdx.x;
    const float4* ps4 = (const float4*)g_psum;   // 5*256 float4
    const float4* pc4 = (const float4*)g_pcnt;

    // all loads independent -> single memory wave
    float4 sv[NUM_CLASSES], cv[NUM_CLASSES];
#pragma unroll
    for (int c = 0; c < NUM_CLASSES; c++) {
        sv[c] = ps4[c * (NBLK / 4) + tid];
        cv[c] = pc4[c * (NBLK / 4) + tid];
    }

    float s[NUM_CLASSES], n[NUM_CLASSES];
#pragma unroll
    for (int c = 0; c < NUM_CLASSES; c++) {
        s[c] = (sv[c].x + sv[c].y) + (sv[c].z + sv[c].w);
        n[c] = (cv[c].x + cv[c].y) + (cv[c].z + cv[c].w);
    }

    // warp shuffle reduce
#pragma unroll
    for (int o = 16; o > 0; o >>= 1) {
#pragma unroll
        for (int c = 0; c < NUM_CLASSES; c++) {
            s[c] += __shfl_down_sync(0xFFFFFFFFu, s[c], o);
            n[c] += __shfl_down_sync(0xFFFFFFFFu, n[c], o);
        }
    }

    __shared__ float ssum[NTHR / 32][NUM_CLASSES];
    __shared__ float scnt[NTHR / 32][NUM_CLASSES];
    const int wid = tid >> 5;
    const int lid = tid & 31;
    if (lid == 0) {
#pragma unroll
        for (int c = 0; c < NUM_CLASSES; c++) { ssum[wid][c] = s[c]; scnt[wid][c] = n[c]; }
    }
    __syncthreads();

    if (tid == 0) {
        float cls_sum[NUM_CLASSES], cls_cnt[NUM_CLASSES];
#pragma unroll
        for (int c = 0; c < NUM_CLASSES; c++) {
            float a = 0.f, b = 0.f;
#pragma unroll
            for (int w = 0; w < NTHR / 32; w++) { a += ssum[w][c]; b += scnt[w][c]; }
            cls_sum[c] = a; cls_cnt[c] = b;
        }
        // remainder rows not covered by 4-row groups (dead code when nrows%4==0)
        for (int r = rem_start; r < nrows; r++) {
            float a[NUM_CLASSES];
            float m = -1e30f;
            for (int c = 0; c < NUM_CLASSES; c++) {
                a[c] = inputs[r * NUM_CLASSES + c];
                m = fmaxf(m, a[c]);
            }
            float se = 0.f;
            for (int c = 0; c < NUM_CLASSES; c++) se += __expf(a[c] - m);
            const int t = targets[r];
            cls_sum[t] += __logf(se) + m - a[t];
            cls_cnt[t] += 1.f;
        }
        float total = 0.f;
#pragma unroll
        for (int c = 0; c < NUM_CLASSES; c++) {
            total += (cls_cnt[c] > 0.f) ? (cls_sum[c] / cls_cnt[c]) : 0.f;
        }
        out[0] = total;
    }
}

extern "C" void kernel_launch(void* const* d_in, const int* in_sizes, int n_in,
                              void* d_out, int out_size)
{
    const float* inputs  = (const float*)d_in[0];
    const int*   targets = (const int*)d_in[1];
    float*       out     = (float*)d_out;

    const int nrows   = in_sizes[0] / NUM_CLASSES;
    const int ngroups = nrows / 4;              // 4 rows per thread-iteration
    const int rem     = ngroups * 4;            // first remainder row

    mfe_main_kernel<<<NBLK, NTHR>>>(
        (const float4*)inputs, (const int4*)targets, ngroups);
    mfe_final_kernel<<<1, NTHR>>>(out, inputs, targets, rem, nrows);
}